// round 10
// baseline (speedup 1.0000x reference)
#include <cuda_runtime.h>
#include <cuda_fp16.h>
#include <cstdint>

#define N_NODES 100000
#define N_EDGES 3200000
#define N_FEAT 128
#define HIDDEN 64
#define N_CLASSES 3
#define N_GRAPHS 512
#define BN_EPS 1e-5f
#define SCAN_T 1024
#define CHUNK ((N_NODES + SCAN_T - 1) / SCAN_T)

// ---- scratch: device globals, accessed ONLY by symbol in device code -------
__device__ __half g_hs[(size_t)N_NODES * HIDDEN];   // X@W in fp16 (unscaled)
__device__ float  g_h1[(size_t)N_NODES * HIDDEN];   // layer-1 output (fp32)
__device__ float  g_dinv[N_NODES];
__device__ int    g_deg[N_NODES];
__device__ int    g_row[N_NODES + 1];               // CSR row offsets (by dst)
__device__ int    g_cur[N_NODES];                   // fill cursors
__device__ int    g_csr[N_EDGES];                   // src list grouped by dst
__device__ float  g_pool[N_GRAPHS * HIDDEN];
__device__ int    g_cnt[N_GRAPHS];
__device__ int    g_e64, g_b64;
__device__ const float* g_prm[10];  // [b1,g1,bt1,rm1,rv1, b2,g2,bt2,rm2,rv2]
__device__ float  g_A[2 * HIDDEN];  // BN scale per layer/channel
__device__ float  g_C[2 * HIDDEN];  // BN shift (bias folded)

// ---- dtype detection (blocked [2,E] layout, C-order) -----------------------
__global__ void detect_kernel(const int* __restrict__ ew,
                              const int* __restrict__ bw) {
    int ez = 1;
    for (int i = 0; i < 64; i++)
        if (ew[2 * i + 1] != 0) ez = 0;
    g_e64 = ez;
    int bz = 1;
    for (int i = 0; i < 64; i++)
        if (bw[50000 + 2 * i + 1] != 0) bz = 0;
    g_b64 = bz;
}

__device__ __forceinline__ int e_src(const void* e, int i, int f64) {
    return f64 ? (int)((const long long*)e)[i] : ((const int*)e)[i];
}
__device__ __forceinline__ int e_dst(const void* e, int i, int f64) {
    return f64 ? (int)((const long long*)e)[(size_t)N_EDGES + i]
               : ((const int*)e)[(size_t)N_EDGES + i];
}
__device__ __forceinline__ int b_at(const void* b, int i, int f64) {
    return f64 ? (int)((const long long*)b)[i] : ((const int*)b)[i];
}

// ---- param classification + BN coefficient precompute ----------------------
__global__ void classify_kernel(const float* p0, const float* p1,
                                const float* p2, const float* p3,
                                const float* p4, const float* p5,
                                const float* p6, const float* p7,
                                const float* p8, const float* p9) {
    const float* ps[10] = {p0, p1, p2, p3, p4, p5, p6, p7, p8, p9};
    const float* bucket[4][4];
    int cnt[4] = {0, 0, 0, 0};
    for (int i = 0; i < 10; i++) {
        bool allz = true, allo = true, anyneg = false;
        for (int k = 0; k < 64; k++) {
            float v = ps[i][k];
            allz = allz && (v == 0.0f);
            allo = allo && (v == 1.0f);
            anyneg = anyneg || (v < 0.0f);
        }
        int t = allz ? 0 : (allo ? 1 : (anyneg ? 2 : 3));
        if (cnt[t] < 4) bucket[t][cnt[t]++] = ps[i];
    }
    if (cnt[0] == 4 && cnt[1] == 2 && cnt[2] == 2 && cnt[3] == 2) {
        g_prm[0] = bucket[0][0]; g_prm[2] = bucket[0][1];
        g_prm[5] = bucket[0][2]; g_prm[7] = bucket[0][3];
        g_prm[1] = bucket[1][0]; g_prm[6] = bucket[1][1];
        g_prm[3] = bucket[2][0]; g_prm[8] = bucket[2][1];
        g_prm[4] = bucket[3][0]; g_prm[9] = bucket[3][1];
    } else {
        for (int i = 0; i < 10; i++) g_prm[i] = ps[i];
    }
    for (int L = 0; L < 2; L++) {
        const float* b     = g_prm[L * 5 + 0];
        const float* gamma = g_prm[L * 5 + 1];
        const float* beta  = g_prm[L * 5 + 2];
        const float* rmean = g_prm[L * 5 + 3];
        const float* rvar  = g_prm[L * 5 + 4];
        for (int c = 0; c < 64; c++) {
            float sc = gamma[c] * rsqrtf(rvar[c] + BN_EPS);
            g_A[L * 64 + c] = sc;
            g_C[L * 64 + c] = beta[c] + (b[c] - rmean[c]) * sc;
        }
    }
}

// ---- zero ------------------------------------------------------------------
__global__ void zero_kernel(float* __restrict__ out, int out_size) {
    int i = blockIdx.x * blockDim.x + threadIdx.x;
    if (i < N_NODES) g_deg[i] = 0;
    if (i < (N_GRAPHS * HIDDEN) / 4)
        ((float4*)g_pool)[i] = make_float4(0.f, 0.f, 0.f, 0.f);
    if (i < N_GRAPHS) g_cnt[i] = 0;
    if (i < out_size) out[i] = 0.f;
}

// ---- degree ----------------------------------------------------------------
__global__ void deg_kernel(const void* __restrict__ edge) {
    int e = blockIdx.x * blockDim.x + threadIdx.x;
    int f = g_e64;
    if (e < N_EDGES) atomicAdd(&g_deg[e_dst(edge, e, f)], 1);
}

// ---- prefix scan -> row offsets, cursors, dinv (single block) --------------
__global__ void scan_kernel() {
    __shared__ int sp[SCAN_T];
    int t = threadIdx.x;
    int lo = t * CHUNK;
    int hi = lo + CHUNK < N_NODES ? lo + CHUNK : N_NODES;
    int s = 0;
    for (int i = lo; i < hi; i++) s += g_deg[i];
    sp[t] = s;
    __syncthreads();
    for (int off = 1; off < SCAN_T; off <<= 1) {
        int v = (t >= off) ? sp[t - off] : 0;
        __syncthreads();
        sp[t] += v;
        __syncthreads();
    }
    int run = (t > 0) ? sp[t - 1] : 0;
    for (int i = lo; i < hi; i++) {
        g_row[i] = run;
        g_cur[i] = run;
        int d = g_deg[i];
        run += d;
        g_dinv[i] = rsqrtf((float)(d + 1));   // +1 self loop
    }
    if (t == SCAN_T - 1) g_row[N_NODES] = run;
}

// ---- CSR fill: group src indices by dst ------------------------------------
__global__ void fill_kernel(const void* __restrict__ edge) {
    int e = blockIdx.x * blockDim.x + threadIdx.x;
    if (e >= N_EDGES) return;
    int f = g_e64;
    int s = e_src(edge, e, f);
    int d = e_dst(edge, e, f);
    int pos = atomicAdd(&g_cur[d], 1);
    g_csr[pos] = s;
}

// ---- pool counts -----------------------------------------------------------
__global__ void pool_cnt_kernel(const void* __restrict__ batch) {
    int n = blockIdx.x * blockDim.x + threadIdx.x;
    int f = g_b64;
    if (n < N_NODES) atomicAdd(&g_cnt[b_at(batch, n, f)], 1);
}

// ---- GEMM: g_hs = fp16(X[N,K] @ W[K,64])  (no dinv — applied in gather) ----
template <int K, bool SRC_H1>
__global__ void gemm_kernel(const float* __restrict__ X,
                            const float* __restrict__ W) {
    __shared__ float xs[64][68];
    __shared__ float ws[64][64];

    const float* Xp = SRC_H1 ? (const float*)g_h1 : X;
    const int t = threadIdx.x;
    const int row0 = blockIdx.x * 64;
    const int tx = t & 15;
    const int ty = t >> 4;
    const int c0 = tx * 4;
    const int r0 = ty * 4;

    float acc[4][4] = {};

    for (int kb = 0; kb < K; kb += 64) {
        for (int i = t; i < 64 * 16; i += 256) {
            int r = i >> 4, c4 = i & 15;
            *(float4*)&ws[r][c4 * 4] =
                *(const float4*)(W + (size_t)(kb + r) * 64 + c4 * 4);
        }
        for (int i = t; i < 64 * 16; i += 256) {
            int r = i >> 4, c4 = i & 15;
            int gr = row0 + r;
            float4 v = make_float4(0.f, 0.f, 0.f, 0.f);
            if (gr < N_NODES)
                v = *(const float4*)(Xp + (size_t)gr * K + kb + c4 * 4);
            *(float4*)&xs[r][c4 * 4] = v;
        }
        __syncthreads();

        #pragma unroll
        for (int k = 0; k < 64; k++) {
            float4 w4 = *(float4*)&ws[k][c0];
            #pragma unroll
            for (int i = 0; i < 4; i++) {
                float xv = xs[r0 + i][k];
                acc[i][0] += xv * w4.x;
                acc[i][1] += xv * w4.y;
                acc[i][2] += xv * w4.z;
                acc[i][3] += xv * w4.w;
            }
        }
        __syncthreads();
    }

    #pragma unroll
    for (int i = 0; i < 4; i++) {
        int gr = row0 + r0 + i;
        if (gr < N_NODES) {
            __half2 h01 = __floats2half2_rn(acc[i][0], acc[i][1]);
            __half2 h23 = __floats2half2_rn(acc[i][2], acc[i][3]);
            uint2 packed = make_uint2(*(unsigned*)&h01, *(unsigned*)&h23);
            *((uint2*)(g_hs + (size_t)gr * HIDDEN) + tx) = packed;
        }
    }
}

// ---- fused gather + norm + BN + ReLU (+ pool for layer 2) ------------------
// One warp per dst node, split into FOUR 8-lane groups. Each group covers the
// whole 128B fp16 row (8 lanes x uint4) and walks every 4th in-edge, unrolled
// x2 -> up to 8 independent row loads in flight per warp (MLP).
__device__ __forceinline__ void acc_row(float* a, int s, int p) {
    float ds = g_dinv[s];
    uint4 raw = *((const uint4*)(g_hs + (size_t)s * HIDDEN) + p);
    float2 f0 = __half22float2(*(__half2*)&raw.x);
    float2 f1 = __half22float2(*(__half2*)&raw.y);
    float2 f2 = __half22float2(*(__half2*)&raw.z);
    float2 f3 = __half22float2(*(__half2*)&raw.w);
    a[0] += ds * f0.x; a[1] += ds * f0.y;
    a[2] += ds * f1.x; a[3] += ds * f1.y;
    a[4] += ds * f2.x; a[5] += ds * f2.y;
    a[6] += ds * f3.x; a[7] += ds * f3.y;
}

template <int LAYER>
__global__ void gather_kernel(const void* __restrict__ batch) {
    int node = (blockIdx.x * blockDim.x + threadIdx.x) >> 5;
    if (node >= N_NODES) return;
    int lane = threadIdx.x & 31;
    int p = lane & 7;       // uint4 index within 128B row
    int grp = lane >> 3;    // 0..3
    int beg = g_row[node], end = g_row[node + 1];

    float a[8] = {0.f, 0.f, 0.f, 0.f, 0.f, 0.f, 0.f, 0.f};

    // unrolled-by-2 walk: 2 independent rows in flight per group
    int i = beg + grp;
    for (; i + 4 < end; i += 8) {
        int s0 = g_csr[i];
        int s1 = g_csr[i + 4];
        acc_row(a, s0, p);
        acc_row(a, s1, p);
    }
    if (i < end) acc_row(a, g_csr[i], p);

    // combine the 4 groups: lanes 0..7 end with the full sum
    #pragma unroll
    for (int j = 0; j < 8; j++) {
        a[j] += __shfl_down_sync(0xffffffffu, a[j], 16);
        a[j] += __shfl_down_sync(0xffffffffu, a[j], 8);
    }

    if (grp == 0) {
        float di = g_dinv[node];
        uint4 raw = *((const uint4*)(g_hs + (size_t)node * HIDDEN) + p);
        float2 s0 = __half22float2(*(__half2*)&raw.x);
        float2 s1 = __half22float2(*(__half2*)&raw.y);
        float2 s2 = __half22float2(*(__half2*)&raw.z);
        float2 s3 = __half22float2(*(__half2*)&raw.w);
        float sv[8] = {s0.x, s0.y, s1.x, s1.y, s2.x, s2.y, s3.x, s3.y};

        float4 A0 = *((const float4*)(g_A + LAYER * HIDDEN) + 2 * p);
        float4 A1 = *((const float4*)(g_A + LAYER * HIDDEN) + 2 * p + 1);
        float4 C0 = *((const float4*)(g_C + LAYER * HIDDEN) + 2 * p);
        float4 C1 = *((const float4*)(g_C + LAYER * HIDDEN) + 2 * p + 1);
        float Av[8] = {A0.x, A0.y, A0.z, A0.w, A1.x, A1.y, A1.z, A1.w};
        float Cv[8] = {C0.x, C0.y, C0.z, C0.w, C1.x, C1.y, C1.z, C1.w};

        float r[8];
        #pragma unroll
        for (int j = 0; j < 8; j++)
            r[j] = fmaxf(di * (a[j] + di * sv[j]) * Av[j] + Cv[j], 0.f);

        if (LAYER == 0) {
            float4* dst = (float4*)(g_h1 + (size_t)node * HIDDEN) + 2 * p;
            dst[0] = make_float4(r[0], r[1], r[2], r[3]);
            dst[1] = make_float4(r[4], r[5], r[6], r[7]);
        } else {
            int g = b_at(batch, node, g_b64);
            float4* dst = (float4*)(g_pool + (size_t)g * HIDDEN) + 2 * p;
            atomicAdd(dst,     make_float4(r[0], r[1], r[2], r[3]));
            atomicAdd(dst + 1, make_float4(r[4], r[5], r[6], r[7]));
        }
    }
}

// ---- classifier ------------------------------------------------------------
__global__ void classify_out_kernel(const float* __restrict__ Wc,
                                    const float* __restrict__ bc,
                                    float* __restrict__ out) {
    int g = blockIdx.x;
    int c = threadIdx.x;   // 64 threads
    float pooled = g_pool[g * HIDDEN + c] / fmaxf((float)g_cnt[g], 1.f);
    __shared__ float sp[HIDDEN];
    sp[c] = pooled;
    __syncthreads();
    if (c < N_CLASSES) {
        float o = __ldg(&bc[c]);
        for (int k = 0; k < HIDDEN; k++)
            o += sp[k] * __ldg(&Wc[k * N_CLASSES + c]);
        out[g * N_CLASSES + c] = o;
    }
}

// ---- launch ----------------------------------------------------------------
extern "C" void kernel_launch(void* const* d_in, const int* in_sizes, int n_in,
                              void* d_out, int out_size) {
    const float *x = 0, *W1 = 0, *W2 = 0, *Wc = 0, *bc = 0;
    const void *edge = 0, *batch = 0;
    const float* v64[10] = {0};
    int n64 = 0;
    for (int i = 0; i < n_in; i++) {
        switch (in_sizes[i]) {
            case 12800000: x     = (const float*)d_in[i]; break;
            case 8192:     W1    = (const float*)d_in[i]; break;
            case 4096:     W2    = (const float*)d_in[i]; break;
            case 192:      Wc    = (const float*)d_in[i]; break;
            case 3:        bc    = (const float*)d_in[i]; break;
            case 6400000:  edge  = d_in[i];               break;
            case 100000:   batch = d_in[i];               break;
            case 64: if (n64 < 10) v64[n64++] = (const float*)d_in[i]; break;
            default: break;
        }
    }
    float* out = (float*)d_out;
    const int T = 256;

    // fork: GEMM1 + pool counts are independent of the CSR-build chain
    cudaStream_t s2;
    cudaStreamCreate(&s2);
    cudaEvent_t evFork, evJoin;
    cudaEventCreateWithFlags(&evFork, cudaEventDisableTiming);
    cudaEventCreateWithFlags(&evJoin, cudaEventDisableTiming);

    cudaEventRecord(evFork, 0);
    cudaStreamWaitEvent(s2, evFork, 0);
    gemm_kernel<N_FEAT, false><<<(N_NODES + 63) / 64, T, 0, s2>>>(x, W1);
    cudaEventRecord(evJoin, s2);

    // main chain: dtype + params + CSR build
    detect_kernel<<<1, 1>>>((const int*)edge, (const int*)batch);
    classify_kernel<<<1, 1>>>(v64[0], v64[1], v64[2], v64[3], v64[4],
                              v64[5], v64[6], v64[7], v64[8], v64[9]);
    zero_kernel<<<(N_NODES + T - 1) / T, T>>>(out, out_size);
    deg_kernel<<<(N_EDGES + T - 1) / T, T>>>(edge);
    pool_cnt_kernel<<<(N_NODES + T - 1) / T, T>>>(batch);
    scan_kernel<<<1, SCAN_T>>>();
    fill_kernel<<<(N_EDGES + T - 1) / T, T>>>(edge);

    // join, then layer 1 gather
    cudaStreamWaitEvent(0, evJoin, 0);
    gather_kernel<0><<<(N_NODES * 32 + T - 1) / T, T>>>(batch);

    // layer 2
    gemm_kernel<HIDDEN, true><<<(N_NODES + 63) / 64, T>>>(0, W2);
    gather_kernel<1><<<(N_NODES * 32 + T - 1) / T, T>>>(batch);

    // classifier
    classify_out_kernel<<<N_GRAPHS, HIDDEN>>>(Wc, bc, out);
}

// round 11
// speedup vs baseline: 1.0389x; 1.0389x over previous
#include <cuda_runtime.h>
#include <cuda_fp16.h>
#include <cstdint>

#define N_NODES 100000
#define N_EDGES 3200000
#define N_FEAT 128
#define HIDDEN 64
#define N_CLASSES 3
#define N_GRAPHS 512
#define BN_EPS 1e-5f
#define SCAN_T 1024
#define CHUNK ((N_NODES + SCAN_T - 1) / SCAN_T)

// ---- scratch: device globals, accessed ONLY by symbol in device code -------
__device__ __half g_hs[(size_t)N_NODES * HIDDEN];   // X@W in fp16 (unscaled)
__device__ float  g_h1[(size_t)N_NODES * HIDDEN];   // layer-1 output (fp32)
__device__ float  g_dinv[N_NODES];
__device__ int    g_deg[N_NODES];
__device__ int    g_row[N_NODES + 1];               // CSR row offsets (by dst)
__device__ int    g_cur[N_NODES];                   // fill cursors
__device__ int    g_csr[N_EDGES];                   // src list grouped by dst
__device__ float  g_pool[N_GRAPHS * HIDDEN];
__device__ int    g_cnt[N_GRAPHS];
__device__ int    g_e64, g_b64;
__device__ const float* g_prm[10];  // [b1,g1,bt1,rm1,rv1, b2,g2,bt2,rm2,rv2]
__device__ float  g_A[2 * HIDDEN];  // BN scale per layer/channel
__device__ float  g_C[2 * HIDDEN];  // BN shift (bias folded)

// ---- dtype detection (blocked [2,E] layout, C-order) -----------------------
__global__ void detect_kernel(const int* __restrict__ ew,
                              const int* __restrict__ bw) {
    int ez = 1;
    for (int i = 0; i < 64; i++)
        if (ew[2 * i + 1] != 0) ez = 0;
    g_e64 = ez;
    int bz = 1;
    for (int i = 0; i < 64; i++)
        if (bw[50000 + 2 * i + 1] != 0) bz = 0;
    g_b64 = bz;
}

__device__ __forceinline__ int e_src(const void* e, int i, int f64) {
    return f64 ? (int)((const long long*)e)[i] : ((const int*)e)[i];
}
__device__ __forceinline__ int e_dst(const void* e, int i, int f64) {
    return f64 ? (int)((const long long*)e)[(size_t)N_EDGES + i]
               : ((const int*)e)[(size_t)N_EDGES + i];
}
__device__ __forceinline__ int b_at(const void* b, int i, int f64) {
    return f64 ? (int)((const long long*)b)[i] : ((const int*)b)[i];
}

// ---- param classification + BN coefficient precompute ----------------------
__global__ void classify_kernel(const float* p0, const float* p1,
                                const float* p2, const float* p3,
                                const float* p4, const float* p5,
                                const float* p6, const float* p7,
                                const float* p8, const float* p9) {
    const float* ps[10] = {p0, p1, p2, p3, p4, p5, p6, p7, p8, p9};
    const float* bucket[4][4];
    int cnt[4] = {0, 0, 0, 0};
    for (int i = 0; i < 10; i++) {
        bool allz = true, allo = true, anyneg = false;
        for (int k = 0; k < 64; k++) {
            float v = ps[i][k];
            allz = allz && (v == 0.0f);
            allo = allo && (v == 1.0f);
            anyneg = anyneg || (v < 0.0f);
        }
        int t = allz ? 0 : (allo ? 1 : (anyneg ? 2 : 3));
        if (cnt[t] < 4) bucket[t][cnt[t]++] = ps[i];
    }
    if (cnt[0] == 4 && cnt[1] == 2 && cnt[2] == 2 && cnt[3] == 2) {
        g_prm[0] = bucket[0][0]; g_prm[2] = bucket[0][1];
        g_prm[5] = bucket[0][2]; g_prm[7] = bucket[0][3];
        g_prm[1] = bucket[1][0]; g_prm[6] = bucket[1][1];
        g_prm[3] = bucket[2][0]; g_prm[8] = bucket[2][1];
        g_prm[4] = bucket[3][0]; g_prm[9] = bucket[3][1];
    } else {
        for (int i = 0; i < 10; i++) g_prm[i] = ps[i];
    }
    for (int L = 0; L < 2; L++) {
        const float* b     = g_prm[L * 5 + 0];
        const float* gamma = g_prm[L * 5 + 1];
        const float* beta  = g_prm[L * 5 + 2];
        const float* rmean = g_prm[L * 5 + 3];
        const float* rvar  = g_prm[L * 5 + 4];
        for (int c = 0; c < 64; c++) {
            float sc = gamma[c] * rsqrtf(rvar[c] + BN_EPS);
            g_A[L * 64 + c] = sc;
            g_C[L * 64 + c] = beta[c] + (b[c] - rmean[c]) * sc;
        }
    }
}

// ---- zero ------------------------------------------------------------------
__global__ void zero_kernel(float* __restrict__ out, int out_size) {
    int i = blockIdx.x * blockDim.x + threadIdx.x;
    if (i < N_NODES) g_deg[i] = 0;
    if (i < (N_GRAPHS * HIDDEN) / 4)
        ((float4*)g_pool)[i] = make_float4(0.f, 0.f, 0.f, 0.f);
    if (i < N_GRAPHS) g_cnt[i] = 0;
    if (i < out_size) out[i] = 0.f;
}

// ---- degree ----------------------------------------------------------------
__global__ void deg_kernel(const void* __restrict__ edge) {
    int e = blockIdx.x * blockDim.x + threadIdx.x;
    int f = g_e64;
    if (e < N_EDGES) atomicAdd(&g_deg[e_dst(edge, e, f)], 1);
}

// ---- prefix scan -> row offsets, cursors, dinv (single block) --------------
__global__ void scan_kernel() {
    __shared__ int sp[SCAN_T];
    int t = threadIdx.x;
    int lo = t * CHUNK;
    int hi = lo + CHUNK < N_NODES ? lo + CHUNK : N_NODES;
    int s = 0;
    for (int i = lo; i < hi; i++) s += g_deg[i];
    sp[t] = s;
    __syncthreads();
    for (int off = 1; off < SCAN_T; off <<= 1) {
        int v = (t >= off) ? sp[t - off] : 0;
        __syncthreads();
        sp[t] += v;
        __syncthreads();
    }
    int run = (t > 0) ? sp[t - 1] : 0;
    for (int i = lo; i < hi; i++) {
        g_row[i] = run;
        g_cur[i] = run;
        int d = g_deg[i];
        run += d;
        g_dinv[i] = rsqrtf((float)(d + 1));   // +1 self loop
    }
    if (t == SCAN_T - 1) g_row[N_NODES] = run;
}

// ---- CSR fill: group src indices by dst ------------------------------------
__global__ void fill_kernel(const void* __restrict__ edge) {
    int e = blockIdx.x * blockDim.x + threadIdx.x;
    if (e >= N_EDGES) return;
    int f = g_e64;
    int s = e_src(edge, e, f);
    int d = e_dst(edge, e, f);
    int pos = atomicAdd(&g_cur[d], 1);
    g_csr[pos] = s;
}

// ---- pool counts -----------------------------------------------------------
__global__ void pool_cnt_kernel(const void* __restrict__ batch) {
    int n = blockIdx.x * blockDim.x + threadIdx.x;
    int f = g_b64;
    if (n < N_NODES) atomicAdd(&g_cnt[b_at(batch, n, f)], 1);
}

// ---- GEMM: g_hs = fp16(X[N,K] @ W[K,64])  (no dinv — applied in gather) ----
template <int K, bool SRC_H1>
__global__ void gemm_kernel(const float* __restrict__ X,
                            const float* __restrict__ W) {
    __shared__ float xs[64][68];
    __shared__ float ws[64][64];

    const float* Xp = SRC_H1 ? (const float*)g_h1 : X;
    const int t = threadIdx.x;
    const int row0 = blockIdx.x * 64;
    const int tx = t & 15;
    const int ty = t >> 4;
    const int c0 = tx * 4;
    const int r0 = ty * 4;

    float acc[4][4] = {};

    for (int kb = 0; kb < K; kb += 64) {
        for (int i = t; i < 64 * 16; i += 256) {
            int r = i >> 4, c4 = i & 15;
            *(float4*)&ws[r][c4 * 4] =
                *(const float4*)(W + (size_t)(kb + r) * 64 + c4 * 4);
        }
        for (int i = t; i < 64 * 16; i += 256) {
            int r = i >> 4, c4 = i & 15;
            int gr = row0 + r;
            float4 v = make_float4(0.f, 0.f, 0.f, 0.f);
            if (gr < N_NODES)
                v = *(const float4*)(Xp + (size_t)gr * K + kb + c4 * 4);
            *(float4*)&xs[r][c4 * 4] = v;
        }
        __syncthreads();

        #pragma unroll
        for (int k = 0; k < 64; k++) {
            float4 w4 = *(float4*)&ws[k][c0];
            #pragma unroll
            for (int i = 0; i < 4; i++) {
                float xv = xs[r0 + i][k];
                acc[i][0] += xv * w4.x;
                acc[i][1] += xv * w4.y;
                acc[i][2] += xv * w4.z;
                acc[i][3] += xv * w4.w;
            }
        }
        __syncthreads();
    }

    #pragma unroll
    for (int i = 0; i < 4; i++) {
        int gr = row0 + r0 + i;
        if (gr < N_NODES) {
            __half2 h01 = __floats2half2_rn(acc[i][0], acc[i][1]);
            __half2 h23 = __floats2half2_rn(acc[i][2], acc[i][3]);
            uint2 packed = make_uint2(*(unsigned*)&h01, *(unsigned*)&h23);
            *((uint2*)(g_hs + (size_t)gr * HIDDEN) + tx) = packed;
        }
    }
}

// ---- fused gather + norm + BN + ReLU (+ pool for layer 2) ------------------
// One warp per dst node; 2 half-warps (16 lanes x uint2 = 128B fp16 row).
// Inner loop unrolled x4 with batched index->dinv->row phases: ~8 independent
// row loads in flight per warp, modest registers (R9 layout, higher MLP).
__device__ __forceinline__ void acc2(float4& a, float ds, uint2 raw) {
    float2 f01 = __half22float2(*(__half2*)&raw.x);
    float2 f23 = __half22float2(*(__half2*)&raw.y);
    a.x += ds * f01.x; a.y += ds * f01.y;
    a.z += ds * f23.x; a.w += ds * f23.y;
}

template <int LAYER>
__global__ void gather_kernel(const void* __restrict__ batch) {
    int node = (blockIdx.x * blockDim.x + threadIdx.x) >> 5;
    if (node >= N_NODES) return;
    int lane = threadIdx.x & 31;
    int p = lane & 15;
    int half = lane >> 4;
    int beg = g_row[node], end = g_row[node + 1];

    float4 a = make_float4(0.f, 0.f, 0.f, 0.f);

    int i = beg + half;
    // 4 edges per iteration per half-warp (stride 2 within half)
    for (; i + 6 < end; i += 8) {
        int s0 = g_csr[i];
        int s1 = g_csr[i + 2];
        int s2 = g_csr[i + 4];
        int s3 = g_csr[i + 6];
        float d0 = g_dinv[s0];
        float d1 = g_dinv[s1];
        float d2 = g_dinv[s2];
        float d3 = g_dinv[s3];
        uint2 r0 = *((const uint2*)(g_hs + (size_t)s0 * HIDDEN) + p);
        uint2 r1 = *((const uint2*)(g_hs + (size_t)s1 * HIDDEN) + p);
        uint2 r2 = *((const uint2*)(g_hs + (size_t)s2 * HIDDEN) + p);
        uint2 r3 = *((const uint2*)(g_hs + (size_t)s3 * HIDDEN) + p);
        acc2(a, d0, r0);
        acc2(a, d1, r1);
        acc2(a, d2, r2);
        acc2(a, d3, r3);
    }
    for (; i < end; i += 2) {
        int s = g_csr[i];
        float ds = g_dinv[s];
        uint2 raw = *((const uint2*)(g_hs + (size_t)s * HIDDEN) + p);
        acc2(a, ds, raw);
    }

    a.x += __shfl_down_sync(0xffffffffu, a.x, 16);
    a.y += __shfl_down_sync(0xffffffffu, a.y, 16);
    a.z += __shfl_down_sync(0xffffffffu, a.z, 16);
    a.w += __shfl_down_sync(0xffffffffu, a.w, 16);

    if (half == 0) {
        float di = g_dinv[node];
        uint2 raw = *((const uint2*)(g_hs + (size_t)node * HIDDEN) + p);
        float2 s01 = __half22float2(*(__half2*)&raw.x);
        float2 s23 = __half22float2(*(__half2*)&raw.y);
        float4 A = *((const float4*)(g_A + LAYER * HIDDEN) + p);
        float4 C = *((const float4*)(g_C + LAYER * HIDDEN) + p);
        float4 r;
        r.x = fmaxf(di * (a.x + di * s01.x) * A.x + C.x, 0.f);
        r.y = fmaxf(di * (a.y + di * s01.y) * A.y + C.y, 0.f);
        r.z = fmaxf(di * (a.z + di * s23.x) * A.z + C.z, 0.f);
        r.w = fmaxf(di * (a.w + di * s23.y) * A.w + C.w, 0.f);
        if (LAYER == 0) {
            *((float4*)(g_h1 + (size_t)node * HIDDEN) + p) = r;
        } else {
            int g = b_at(batch, node, g_b64);
            atomicAdd((float4*)(g_pool + (size_t)g * HIDDEN) + p, r);
        }
    }
}

// ---- classifier ------------------------------------------------------------
__global__ void classify_out_kernel(const float* __restrict__ Wc,
                                    const float* __restrict__ bc,
                                    float* __restrict__ out) {
    int g = blockIdx.x;
    int c = threadIdx.x;   // 64 threads
    float pooled = g_pool[g * HIDDEN + c] / fmaxf((float)g_cnt[g], 1.f);
    __shared__ float sp[HIDDEN];
    sp[c] = pooled;
    __syncthreads();
    if (c < N_CLASSES) {
        float o = __ldg(&bc[c]);
        for (int k = 0; k < HIDDEN; k++)
            o += sp[k] * __ldg(&Wc[k * N_CLASSES + c]);
        out[g * N_CLASSES + c] = o;
    }
}

// ---- launch ----------------------------------------------------------------
extern "C" void kernel_launch(void* const* d_in, const int* in_sizes, int n_in,
                              void* d_out, int out_size) {
    const float *x = 0, *W1 = 0, *W2 = 0, *Wc = 0, *bc = 0;
    const void *edge = 0, *batch = 0;
    const float* v64[10] = {0};
    int n64 = 0;
    for (int i = 0; i < n_in; i++) {
        switch (in_sizes[i]) {
            case 12800000: x     = (const float*)d_in[i]; break;
            case 8192:     W1    = (const float*)d_in[i]; break;
            case 4096:     W2    = (const float*)d_in[i]; break;
            case 192:      Wc    = (const float*)d_in[i]; break;
            case 3:        bc    = (const float*)d_in[i]; break;
            case 6400000:  edge  = d_in[i];               break;
            case 100000:   batch = d_in[i];               break;
            case 64: if (n64 < 10) v64[n64++] = (const float*)d_in[i]; break;
            default: break;
        }
    }
    float* out = (float*)d_out;
    const int T = 256;

    // fork: GEMM1 is independent of the CSR-build chain
    cudaStream_t s2;
    cudaStreamCreate(&s2);
    cudaEvent_t evFork, evJoin;
    cudaEventCreateWithFlags(&evFork, cudaEventDisableTiming);
    cudaEventCreateWithFlags(&evJoin, cudaEventDisableTiming);

    cudaEventRecord(evFork, 0);
    cudaStreamWaitEvent(s2, evFork, 0);
    gemm_kernel<N_FEAT, false><<<(N_NODES + 63) / 64, T, 0, s2>>>(x, W1);
    cudaEventRecord(evJoin, s2);

    // main chain: dtype + params + CSR build
    detect_kernel<<<1, 1>>>((const int*)edge, (const int*)batch);
    classify_kernel<<<1, 1>>>(v64[0], v64[1], v64[2], v64[3], v64[4],
                              v64[5], v64[6], v64[7], v64[8], v64[9]);
    zero_kernel<<<(N_NODES + T - 1) / T, T>>>(out, out_size);
    deg_kernel<<<(N_EDGES + T - 1) / T, T>>>(edge);
    pool_cnt_kernel<<<(N_NODES + T - 1) / T, T>>>(batch);
    scan_kernel<<<1, SCAN_T>>>();
    fill_kernel<<<(N_EDGES + T - 1) / T, T>>>(edge);

    // join, then layer 1 gather
    cudaStreamWaitEvent(0, evJoin, 0);
    gather_kernel<0><<<(N_NODES * 32 + T - 1) / T, T>>>(batch);

    // layer 2
    gemm_kernel<HIDDEN, true><<<(N_NODES + 63) / 64, T>>>(0, W2);
    gather_kernel<1><<<(N_NODES * 32 + T - 1) / T, T>>>(batch);

    // classifier
    classify_out_kernel<<<N_GRAPHS, HIDDEN>>>(Wc, bc, out);
}

// round 12
// speedup vs baseline: 1.0559x; 1.0164x over previous
#include <cuda_runtime.h>
#include <cuda_fp16.h>
#include <cstdint>

#define N_NODES 100000
#define N_EDGES 3200000
#define N_FEAT 128
#define HIDDEN 64
#define N_CLASSES 3
#define N_GRAPHS 512
#define BN_EPS 1e-5f
#define SCAN_T 1024
#define CHUNK ((N_NODES + SCAN_T - 1) / SCAN_T)

// ---- scratch: device globals, accessed ONLY by symbol in device code -------
__device__ __half g_hs[(size_t)N_NODES * HIDDEN];   // dinv-scaled X@W in fp16
__device__ float  g_h1[(size_t)N_NODES * HIDDEN];   // layer-1 output (fp32)
__device__ float  g_dinv[N_NODES];
__device__ int    g_deg[N_NODES];
__device__ int    g_row[N_NODES + 1];               // CSR row offsets (by dst)
__device__ int    g_cur[N_NODES];                   // fill cursors
__device__ int    g_csr[N_EDGES];                   // src list grouped by dst
__device__ float  g_pool[N_GRAPHS * HIDDEN];
__device__ int    g_cnt[N_GRAPHS];
__device__ int    g_e64, g_b64;
__device__ float  g_A[2 * HIDDEN];  // BN scale per layer/channel
__device__ float  g_C[2 * HIDDEN];  // BN shift (bias folded)

__device__ __forceinline__ int b_at(const void* b, int i, int f64) {
    return f64 ? (int)((const long long*)b)[i] : ((const int*)b)[i];
}

// ---- setup: dtype detect + param classification + BN precompute (1 thread) -
__global__ void setup_kernel(const int* __restrict__ ew,
                             const int* __restrict__ bw,
                             const float* p0, const float* p1,
                             const float* p2, const float* p3,
                             const float* p4, const float* p5,
                             const float* p6, const float* p7,
                             const float* p8, const float* p9) {
    // dtype: odd 32-bit words all zero  <=>  int64 (high halves of small vals)
    int ez = 1, bz = 1;
    for (int i = 0; i < 64; i++) {
        if (ew[2 * i + 1] != 0) ez = 0;
        if (bw[50000 + 2 * i + 1] != 0) bz = 0;
    }
    g_e64 = ez;
    g_b64 = bz;

    // classify the ten 64-vectors by content (order-proof)
    const float* ps[10] = {p0, p1, p2, p3, p4, p5, p6, p7, p8, p9};
    const float* prm[10];
    const float* bucket[4][4];
    int cnt[4] = {0, 0, 0, 0};
    for (int i = 0; i < 10; i++) {
        bool allz = true, allo = true, anyneg = false;
        for (int k = 0; k < 64; k++) {
            float v = ps[i][k];
            allz = allz && (v == 0.0f);
            allo = allo && (v == 1.0f);
            anyneg = anyneg || (v < 0.0f);
        }
        int t = allz ? 0 : (allo ? 1 : (anyneg ? 2 : 3));
        if (cnt[t] < 4) bucket[t][cnt[t]++] = ps[i];
    }
    if (cnt[0] == 4 && cnt[1] == 2 && cnt[2] == 2 && cnt[3] == 2) {
        prm[0] = bucket[0][0]; prm[2] = bucket[0][1];
        prm[5] = bucket[0][2]; prm[7] = bucket[0][3];
        prm[1] = bucket[1][0]; prm[6] = bucket[1][1];
        prm[3] = bucket[2][0]; prm[8] = bucket[2][1];
        prm[4] = bucket[3][0]; prm[9] = bucket[3][1];
    } else {
        for (int i = 0; i < 10; i++) prm[i] = ps[i];
    }
    for (int L = 0; L < 2; L++) {
        const float* b     = prm[L * 5 + 0];
        const float* gamma = prm[L * 5 + 1];
        const float* beta  = prm[L * 5 + 2];
        const float* rmean = prm[L * 5 + 3];
        const float* rvar  = prm[L * 5 + 4];
        for (int c = 0; c < 64; c++) {
            float sc = gamma[c] * rsqrtf(rvar[c] + BN_EPS);
            g_A[L * 64 + c] = sc;
            g_C[L * 64 + c] = beta[c] + (b[c] - rmean[c]) * sc;
        }
    }
}

// ---- init ------------------------------------------------------------------
__global__ void init_kernel(float* __restrict__ out, int out_size) {
    int i = blockIdx.x * blockDim.x + threadIdx.x;
    if (i < N_NODES) g_deg[i] = 0;
    if (i < (N_GRAPHS * HIDDEN) / 4)
        ((float4*)g_pool)[i] = make_float4(0.f, 0.f, 0.f, 0.f);
    if (i < N_GRAPHS) g_cnt[i] = 0;
    if (i < out_size) out[i] = 0.f;
}

// ---- degree: 4 edges per thread, vectorized index reads --------------------
__global__ void deg_kernel(const void* __restrict__ edge) {
    int t = blockIdx.x * blockDim.x + threadIdx.x;
    if (t >= N_EDGES / 4) return;
    if (g_e64) {
        const longlong2* d2 = (const longlong2*)((const long long*)edge + N_EDGES);
        longlong2 a = d2[2 * t];
        longlong2 b = d2[2 * t + 1];
        atomicAdd(&g_deg[(int)a.x], 1);
        atomicAdd(&g_deg[(int)a.y], 1);
        atomicAdd(&g_deg[(int)b.x], 1);
        atomicAdd(&g_deg[(int)b.y], 1);
    } else {
        int4 d = ((const int4*)((const int*)edge + N_EDGES))[t];
        atomicAdd(&g_deg[d.x], 1);
        atomicAdd(&g_deg[d.y], 1);
        atomicAdd(&g_deg[d.z], 1);
        atomicAdd(&g_deg[d.w], 1);
    }
}

// ---- prefix scan -> row offsets, cursors, dinv (single block) --------------
__global__ void scan_kernel() {
    __shared__ int sp[SCAN_T];
    int t = threadIdx.x;
    int lo = t * CHUNK;
    int hi = lo + CHUNK < N_NODES ? lo + CHUNK : N_NODES;
    int s = 0;
    for (int i = lo; i < hi; i++) s += g_deg[i];
    sp[t] = s;
    __syncthreads();
    for (int off = 1; off < SCAN_T; off <<= 1) {
        int v = (t >= off) ? sp[t - off] : 0;
        __syncthreads();
        sp[t] += v;
        __syncthreads();
    }
    int run = (t > 0) ? sp[t - 1] : 0;
    for (int i = lo; i < hi; i++) {
        g_row[i] = run;
        g_cur[i] = run;
        int d = g_deg[i];
        run += d;
        g_dinv[i] = rsqrtf((float)(d + 1));   // +1 self loop
    }
    if (t == SCAN_T - 1) g_row[N_NODES] = run;
}

// ---- CSR fill: 4 edges per thread ------------------------------------------
__global__ void fill_kernel(const void* __restrict__ edge) {
    int t = blockIdx.x * blockDim.x + threadIdx.x;
    if (t >= N_EDGES / 4) return;
    int s0, s1, s2, s3, d0, d1, d2, d3;
    if (g_e64) {
        const longlong2* sp2 = (const longlong2*)edge;
        const longlong2* dp2 = (const longlong2*)((const long long*)edge + N_EDGES);
        longlong2 sa = sp2[2 * t], sb = sp2[2 * t + 1];
        longlong2 da = dp2[2 * t], db = dp2[2 * t + 1];
        s0 = (int)sa.x; s1 = (int)sa.y; s2 = (int)sb.x; s3 = (int)sb.y;
        d0 = (int)da.x; d1 = (int)da.y; d2 = (int)db.x; d3 = (int)db.y;
    } else {
        int4 s4 = ((const int4*)edge)[t];
        int4 d4 = ((const int4*)((const int*)edge + N_EDGES))[t];
        s0 = s4.x; s1 = s4.y; s2 = s4.z; s3 = s4.w;
        d0 = d4.x; d1 = d4.y; d2 = d4.z; d3 = d4.w;
    }
    g_csr[atomicAdd(&g_cur[d0], 1)] = s0;
    g_csr[atomicAdd(&g_cur[d1], 1)] = s1;
    g_csr[atomicAdd(&g_cur[d2], 1)] = s2;
    g_csr[atomicAdd(&g_cur[d3], 1)] = s3;
}

// ---- pool counts -----------------------------------------------------------
__global__ void pool_cnt_kernel(const void* __restrict__ batch) {
    int n = blockIdx.x * blockDim.x + threadIdx.x;
    int f = g_b64;
    if (n < N_NODES) atomicAdd(&g_cnt[b_at(batch, n, f)], 1);
}

// ---- GEMM: g_hs = fp16( (X[N,K] @ W[K,64]) [* dinv[row] if SCALE] ) --------
template <int K, bool SRC_H1, bool SCALE>
__global__ void gemm_kernel(const float* __restrict__ X,
                            const float* __restrict__ W) {
    __shared__ float xs[64][68];
    __shared__ float ws[64][64];

    const float* Xp = SRC_H1 ? (const float*)g_h1 : X;
    const int t = threadIdx.x;
    const int row0 = blockIdx.x * 64;
    const int tx = t & 15;
    const int ty = t >> 4;
    const int c0 = tx * 4;
    const int r0 = ty * 4;

    float acc[4][4] = {};

    for (int kb = 0; kb < K; kb += 64) {
        for (int i = t; i < 64 * 16; i += 256) {
            int r = i >> 4, c4 = i & 15;
            *(float4*)&ws[r][c4 * 4] =
                *(const float4*)(W + (size_t)(kb + r) * 64 + c4 * 4);
        }
        for (int i = t; i < 64 * 16; i += 256) {
            int r = i >> 4, c4 = i & 15;
            int gr = row0 + r;
            float4 v = make_float4(0.f, 0.f, 0.f, 0.f);
            if (gr < N_NODES)
                v = *(const float4*)(Xp + (size_t)gr * K + kb + c4 * 4);
            *(float4*)&xs[r][c4 * 4] = v;
        }
        __syncthreads();

        #pragma unroll
        for (int k = 0; k < 64; k++) {
            float4 w4 = *(float4*)&ws[k][c0];
            #pragma unroll
            for (int i = 0; i < 4; i++) {
                float xv = xs[r0 + i][k];
                acc[i][0] += xv * w4.x;
                acc[i][1] += xv * w4.y;
                acc[i][2] += xv * w4.z;
                acc[i][3] += xv * w4.w;
            }
        }
        __syncthreads();
    }

    #pragma unroll
    for (int i = 0; i < 4; i++) {
        int gr = row0 + r0 + i;
        if (gr < N_NODES) {
            float s = SCALE ? g_dinv[gr] : 1.0f;
            __half2 h01 = __floats2half2_rn(acc[i][0] * s, acc[i][1] * s);
            __half2 h23 = __floats2half2_rn(acc[i][2] * s, acc[i][3] * s);
            uint2 packed = make_uint2(*(unsigned*)&h01, *(unsigned*)&h23);
            *((uint2*)(g_hs + (size_t)gr * HIDDEN) + tx) = packed;
        }
    }
}

// ---- scale hs rows by dinv (layer-1 only; keeps GEMM1 independent of scan) -
__global__ void scale_hs_kernel() {
    int i = blockIdx.x * blockDim.x + threadIdx.x;   // over uint4 (8 halves)
    if (i >= N_NODES * 8) return;
    float di = g_dinv[i >> 3];
    uint4 raw = ((uint4*)g_hs)[i];
    float2 f0 = __half22float2(*(__half2*)&raw.x);
    float2 f1 = __half22float2(*(__half2*)&raw.y);
    float2 f2 = __half22float2(*(__half2*)&raw.z);
    float2 f3 = __half22float2(*(__half2*)&raw.w);
    __half2 h0 = __floats2half2_rn(f0.x * di, f0.y * di);
    __half2 h1 = __floats2half2_rn(f1.x * di, f1.y * di);
    __half2 h2 = __floats2half2_rn(f2.x * di, f2.y * di);
    __half2 h3 = __floats2half2_rn(f3.x * di, f3.y * di);
    ((uint4*)g_hs)[i] = make_uint4(*(unsigned*)&h0, *(unsigned*)&h1,
                                   *(unsigned*)&h2, *(unsigned*)&h3);
}

// ---- fused gather + BN + ReLU (+ pool for layer 2) -------------------------
// Rows are pre-scaled by dinv[src]: out = di*(Σ hp[s] + hp[node]), then BN.
__device__ __forceinline__ void acc2(float4& a, uint2 raw) {
    float2 f01 = __half22float2(*(__half2*)&raw.x);
    float2 f23 = __half22float2(*(__half2*)&raw.y);
    a.x += f01.x; a.y += f01.y;
    a.z += f23.x; a.w += f23.y;
}

template <int LAYER>
__global__ void gather_kernel(const void* __restrict__ batch) {
    int node = (blockIdx.x * blockDim.x + threadIdx.x) >> 5;
    if (node >= N_NODES) return;
    int lane = threadIdx.x & 31;
    int p = lane & 15;
    int half = lane >> 4;
    int beg = g_row[node], end = g_row[node + 1];

    float4 a = make_float4(0.f, 0.f, 0.f, 0.f);

    int i = beg + half;
    for (; i + 6 < end; i += 8) {
        int s0 = g_csr[i];
        int s1 = g_csr[i + 2];
        int s2 = g_csr[i + 4];
        int s3 = g_csr[i + 6];
        uint2 r0 = *((const uint2*)(g_hs + (size_t)s0 * HIDDEN) + p);
        uint2 r1 = *((const uint2*)(g_hs + (size_t)s1 * HIDDEN) + p);
        uint2 r2 = *((const uint2*)(g_hs + (size_t)s2 * HIDDEN) + p);
        uint2 r3 = *((const uint2*)(g_hs + (size_t)s3 * HIDDEN) + p);
        acc2(a, r0);
        acc2(a, r1);
        acc2(a, r2);
        acc2(a, r3);
    }
    for (; i < end; i += 2) {
        int s = g_csr[i];
        uint2 raw = *((const uint2*)(g_hs + (size_t)s * HIDDEN) + p);
        acc2(a, raw);
    }

    a.x += __shfl_down_sync(0xffffffffu, a.x, 16);
    a.y += __shfl_down_sync(0xffffffffu, a.y, 16);
    a.z += __shfl_down_sync(0xffffffffu, a.z, 16);
    a.w += __shfl_down_sync(0xffffffffu, a.w, 16);

    if (half == 0) {
        float di = g_dinv[node];
        uint2 raw = *((const uint2*)(g_hs + (size_t)node * HIDDEN) + p);
        float2 s01 = __half22float2(*(__half2*)&raw.x);
        float2 s23 = __half22float2(*(__half2*)&raw.y);
        float4 A = *((const float4*)(g_A + LAYER * HIDDEN) + p);
        float4 C = *((const float4*)(g_C + LAYER * HIDDEN) + p);
        float4 r;
        r.x = fmaxf(di * (a.x + s01.x) * A.x + C.x, 0.f);
        r.y = fmaxf(di * (a.y + s01.y) * A.y + C.y, 0.f);
        r.z = fmaxf(di * (a.z + s23.x) * A.z + C.z, 0.f);
        r.w = fmaxf(di * (a.w + s23.y) * A.w + C.w, 0.f);
        if (LAYER == 0) {
            *((float4*)(g_h1 + (size_t)node * HIDDEN) + p) = r;
        } else {
            int g = b_at(batch, node, g_b64);
            atomicAdd((float4*)(g_pool + (size_t)g * HIDDEN) + p, r);
        }
    }
}

// ---- classifier ------------------------------------------------------------
__global__ void classify_out_kernel(const float* __restrict__ Wc,
                                    const float* __restrict__ bc,
                                    float* __restrict__ out) {
    int g = blockIdx.x;
    int c = threadIdx.x;   // 64 threads
    float pooled = g_pool[g * HIDDEN + c] / fmaxf((float)g_cnt[g], 1.f);
    __shared__ float sp[HIDDEN];
    sp[c] = pooled;
    __syncthreads();
    if (c < N_CLASSES) {
        float o = __ldg(&bc[c]);
        for (int k = 0; k < HIDDEN; k++)
            o += sp[k] * __ldg(&Wc[k * N_CLASSES + c]);
        out[g * N_CLASSES + c] = o;
    }
}

// ---- launch ----------------------------------------------------------------
extern "C" void kernel_launch(void* const* d_in, const int* in_sizes, int n_in,
                              void* d_out, int out_size) {
    const float *x = 0, *W1 = 0, *W2 = 0, *Wc = 0, *bc = 0;
    const void *edge = 0, *batch = 0;
    const float* v64[10] = {0};
    int n64 = 0;
    for (int i = 0; i < n_in; i++) {
        switch (in_sizes[i]) {
            case 12800000: x     = (const float*)d_in[i]; break;
            case 8192:     W1    = (const float*)d_in[i]; break;
            case 4096:     W2    = (const float*)d_in[i]; break;
            case 192:      Wc    = (const float*)d_in[i]; break;
            case 3:        bc    = (const float*)d_in[i]; break;
            case 6400000:  edge  = d_in[i];               break;
            case 100000:   batch = d_in[i];               break;
            case 64: if (n64 < 10) v64[n64++] = (const float*)d_in[i]; break;
            default: break;
        }
    }
    float* out = (float*)d_out;
    const int T = 256;

    // fork: GEMM1 (unscaled) is independent of the CSR-build chain
    cudaStream_t s2;
    cudaStreamCreate(&s2);
    cudaEvent_t evFork, evJoin;
    cudaEventCreateWithFlags(&evFork, cudaEventDisableTiming);
    cudaEventCreateWithFlags(&evJoin, cudaEventDisableTiming);

    cudaEventRecord(evFork, 0);
    cudaStreamWaitEvent(s2, evFork, 0);
    gemm_kernel<N_FEAT, false, false><<<(N_NODES + 63) / 64, T, 0, s2>>>(x, W1);
    cudaEventRecord(evJoin, s2);

    // main chain: setup + CSR build
    setup_kernel<<<1, 1>>>((const int*)edge, (const int*)batch,
                           v64[0], v64[1], v64[2], v64[3], v64[4],
                           v64[5], v64[6], v64[7], v64[8], v64[9]);
    init_kernel<<<(N_NODES + T - 1) / T, T>>>(out, out_size);
    deg_kernel<<<(N_EDGES / 4 + T - 1) / T, T>>>(edge);
    scan_kernel<<<1, SCAN_T>>>();
    fill_kernel<<<(N_EDGES / 4 + T - 1) / T, T>>>(edge);
    pool_cnt_kernel<<<(N_NODES + T - 1) / T, T>>>(batch);

    // join, scale hs by dinv, then layer-1 gather
    cudaStreamWaitEvent(0, evJoin, 0);
    scale_hs_kernel<<<(N_NODES * 8 + T - 1) / T, T>>>();
    gather_kernel<0><<<(N_NODES * 32 + T - 1) / T, T>>>(batch);

    // layer 2 (dinv folded into GEMM epilogue)
    gemm_kernel<HIDDEN, true, true><<<(N_NODES + 63) / 64, T>>>(0, W2);
    gather_kernel<1><<<(N_NODES * 32 + T - 1) / T, T>>>(batch);

    // classifier
    classify_out_kernel<<<N_GRAPHS, HIDDEN>>>(Wc, bc, out);
}